// round 9
// baseline (speedup 1.0000x reference)
#include <cuda_runtime.h>
#include <math.h>

#define BB   4
#define NATN 1024

typedef unsigned long long ull;

// scratch: DR descriptors (B*NAT, 1600) and type-sorted atom list
__device__ float g_DR[(size_t)BB * NATN * 1600];
__device__ int   g_sorted_n[1032];

// ---------------- packed f32x2 helpers (SASS FFMA2) ----------------
__device__ __forceinline__ ull pack2(float lo, float hi)
{
    ull r;
    asm("mov.b64 %0, {%1, %2};" : "=l"(r) : "f"(lo), "f"(hi));
    return r;
}
__device__ __forceinline__ void unpack2(ull v, float& lo, float& hi)
{
    asm("mov.b64 {%0, %1}, %2;" : "=f"(lo), "=f"(hi) : "l"(v));
}
__device__ __forceinline__ ull ffma2(ull a, ull b, ull c)
{
    ull d;
    asm("fma.rn.f32x2 %0, %1, %2, %3;" : "=l"(d) : "l"(a), "l"(b), "l"(c));
    return d;
}

// Exact-path lean tanh: 1 - 2*rcp(exp(2x)+1).
// 5 SASS ops, branch-free, overflow-safe. Rel err ~1e-6.
// (tanh.approx.f32 contributes ~5e-4 to final rel_err — not used.)
__device__ __forceinline__ float fast_tanh(float x)
{
    float e = __expf(2.0f * x);
    float r;
    asm("rcp.approx.f32 %0, %1;" : "=f"(r) : "f"(e + 1.0f));
    return fmaf(-2.0f, r, 1.0f);
}

// ---------------------------------------------------------------------------
// Kernel 0: deterministic partition of n-indices by atom type (single block)
// ---------------------------------------------------------------------------
__global__ void sort_kernel(const int* __restrict__ tmap)
{
    __shared__ int sa[1024], sb[1024];
    int tid = threadIdx.x;
    int myt = tmap[tid];
    sa[tid] = (myt == 0) ? 1 : 0;
    __syncthreads();
    int* cur = sa; int* nxt = sb;
    for (int off = 1; off < 1024; off <<= 1) {
        int v = cur[tid];
        if (tid >= off) v += cur[tid - off];
        __syncthreads();
        nxt[tid] = v;
        __syncthreads();
        int* tpp = cur; cur = nxt; nxt = tpp;
    }
    int scan0 = cur[tid];
    int cnt0  = cur[1023];

    g_sorted_n[tid] = -1;
    if (tid < 8) g_sorted_n[1024 + tid] = -1;
    __syncthreads();

    if (myt == 0) {
        g_sorted_n[scan0 - 1] = tid;
    } else {
        int base1 = ((cnt0 + 3) >> 2) << 2;
        g_sorted_n[base1 + tid - scan0] = tid;
    }
}

// ---------------------------------------------------------------------------
// Kernel 1: embedding net + xyz + DR. One block = atom, 224 threads,
// 3 CTAs/SM (21 warps) for latency hiding. f32x2 mainloops.
// Shared layout (floats):
//   sW0   [0,228)      sB0 [228,256)    sW1p [256,1556) 25x52
//   sB1   [1556,1608)  sW2p[1608,7208)  50 x (4 chunks x 28)
//   sB2p  [7208,7320)  sBias[7320,7372)
//   sRiT  [7372,8188)  4 x 204          sGT  [8188,13288) 25 x 204
//   sXYZ  [13288,13688)
// total 13688 floats = 54752 B -> 3 CTAs/SM by smem (164 KB)
// ---------------------------------------------------------------------------
#define ETHR 224
__global__ void __launch_bounds__(ETHR, 3) embed_kernel(
    const float4* __restrict__ imdr,
    const int*    __restrict__ tmap,
    const float4* __restrict__ davg,
    const float4* __restrict__ dstd,
    const float*  __restrict__ type_vector,
    const float*  __restrict__ tW0, const float* __restrict__ tb0,
    const float*  __restrict__ eW0, const float* __restrict__ eb0,
    const float*  __restrict__ eW1, const float* __restrict__ eb1,
    const float*  __restrict__ eW2, const float* __restrict__ eb2)
{
    extern __shared__ float sm[];
    float* sW0  = sm;
    float* sB0  = sm + 228;
    float* sW1p = sm + 256;
    float* sB1  = sm + 1556;
    float* sW2p = sm + 1608;
    float* sB2p = sm + 7208;
    float* sBias= sm + 7320;
    float* sRiT = sm + 7372;
    float* sGT  = sm + 8188;
    float* sXYZ = sm + 13288;

    int tid = threadIdx.x;
    int a = blockIdx.x;
    int n = a & 1023;
    int t = tmap[n];

    for (int i = tid; i < 225; i += ETHR) sW0[i] = eW0[i];
    for (int i = tid; i < 25;  i += ETHR) sB0[i] = eb0[i];
    for (int i = tid; i < 25 * 52; i += ETHR) {
        int row = i / 52, m = i - row * 52;
        sW1p[i] = (m < 50) ? eW1[row * 50 + m] : 0.0f;
    }
    for (int i = tid; i < 50;  i += ETHR) sB1[i] = eb1[i];
    for (int i = tid; i < 50 * 112; i += ETHR) {
        int k = i / 112, rem = i - k * 112;
        int c = rem / 28, m = rem - c * 28;
        sW2p[i] = (m < 25) ? eW2[k * 100 + c * 25 + m] : 0.0f;
    }
    for (int i = tid; i < 112; i += ETHR) {
        int c = i / 28, m = i - c * 28;
        sB2p[i] = (m < 25) ? eb2[c * 25 + m] : 0.0f;
    }
    __syncthreads();

    bool act = (tid < 200);
    float h1[50];
    float ri0 = 0.0f;
    int   nt  = 0;

    if (act) {
        int j = tid;
        nt = (j >= 100) ? 1 : 0;
        float4 im = imdr[(size_t)a * 200 + j];
        float r = im.x;
        float invr = (r > 1e-5f) ? (1.0f / r) : 1.0f;
        float u  = (r - 0.5f) * (1.0f / 5.5f);
        float u2 = u * u;
        float smid = invr * (u * u2 * (-6.0f * u2 + 15.0f * u - 10.0f) + 1.0f);
        float srij = 0.0f;
        if (r > 0.0f && r < 0.5f)        srij = invr;
        else if (r >= 0.5f && r < 6.0f)  srij = smid;
        bool msk = fabsf(r) > 1e-5f;
        float v0 = srij;
        float v1 = msk ? srij * im.y * invr : 0.0f;
        float v2 = msk ? srij * im.z * invr : 0.0f;
        float v3 = msk ? srij * im.w * invr : 0.0f;
        float4 da = davg[t * 200 + j];
        float4 ds = dstd[t * 200 + j];
        v0 = (v0 - da.x) / ds.x;
        v1 = (v1 - da.y) / ds.y;
        v2 = (v2 - da.z) / ds.z;
        v3 = (v3 - da.w) / ds.w;
        sRiT[0 * 204 + j] = v0;
        sRiT[1 * 204 + j] = v1;
        sRiT[2 * 204 + j] = v2;
        sRiT[3 * 204 + j] = v3;
        ri0 = v0;
    } else {
        // folded layer0 bias on threads 200-223 (24 threads, 50 outputs):
        // sBias[t][m] = eb0[m] + sum_k nf_t[k]*eW0[1+k][m]
        for (int i = tid - 200; i < 50; i += ETHR - 200) {
            int tt = i / 25, m = i - tt * 25;
            float tv[4];
            #pragma unroll
            for (int p = 0; p < 4; p++) tv[p] = type_vector[tt * 4 + p];
            float bias = sB0[m];
            #pragma unroll
            for (int k = 0; k < 8; k++) {
                float acc = tb0[k];
                #pragma unroll
                for (int p = 0; p < 4; p++) acc += tv[p] * tW0[p * 8 + k];
                float nfk = fast_tanh(acc) + tv[k & 3];
                bias += nfk * sW0[(k + 1) * 25 + m];
            }
            sBias[tt * 25 + m] = bias;
        }
    }
    __syncthreads();

    if (act) {
        // layer0
        float h0[25];
        #pragma unroll
        for (int m = 0; m < 25; m++)
            h0[m] = fast_tanh(sBias[nt * 25 + m] + ri0 * sW0[m]);

        // layer1: 25 -> 50 with f32x2 accumulators (25 pairs)
        ull h1p[25];
        #pragma unroll
        for (int m = 0; m < 25; m++) h1p[m] = *(const ull*)(sB1 + 2 * m);
        #pragma unroll 5
        for (int k = 0; k < 25; k++) {
            ull hkp = pack2(h0[k], h0[k]);
            const ulonglong2* w2 = (const ulonglong2*)(sW1p + k * 52);
            #pragma unroll
            for (int q = 0; q < 12; q++) {
                ulonglong2 w = w2[q];
                h1p[2 * q]     = ffma2(hkp, w.x, h1p[2 * q]);
                h1p[2 * q + 1] = ffma2(hkp, w.y, h1p[2 * q + 1]);
            }
            ull wl = *(const ull*)(sW1p + k * 52 + 48);
            h1p[24] = ffma2(hkp, wl, h1p[24]);
        }
        #pragma unroll
        for (int m = 0; m < 25; m++) {
            float lo, hi;
            unpack2(h1p[m], lo, hi);
            int i0 = 2 * m, i1 = 2 * m + 1;
            h1[i0] = fast_tanh(lo) + h0[(i0 < 25) ? i0 : (i0 - 25)];
            h1[i1] = fast_tanh(hi) + h0[(i1 < 25) ? i1 : (i1 - 25)];
        }
    }

    // layer2 (50 -> 100) in four 25-wide chunks; f32x2 accumulators.
    for (int c = 0; c < 4; c++) {
        if (act) {
            int j = tid;
            ull accp[12];
            #pragma unroll
            for (int q = 0; q < 12; q++)
                accp[q] = *(const ull*)(sB2p + c * 28 + 2 * q);
            float acc24 = sB2p[c * 28 + 24];
            #pragma unroll 2
            for (int k = 0; k < 50; k++) {
                float hk = h1[k];
                ull hkp = pack2(hk, hk);
                const float* wrow = sW2p + k * 112 + c * 28;
                const ulonglong2* w4 = (const ulonglong2*)wrow;
                #pragma unroll
                for (int q = 0; q < 6; q++) {
                    ulonglong2 w = w4[q];
                    accp[2 * q]     = ffma2(hkp, w.x, accp[2 * q]);
                    accp[2 * q + 1] = ffma2(hkp, w.y, accp[2 * q + 1]);
                }
                acc24 += hk * wrow[24];
            }
            int roff = (c & 1) * 25;
            #pragma unroll
            for (int q = 0; q < 12; q++) {
                float lo, hi;
                unpack2(accp[q], lo, hi);
                sGT[(2 * q)     * 204 + j] = fast_tanh(lo) + h1[roff + 2 * q];
                sGT[(2 * q + 1) * 204 + j] = fast_tanh(hi) + h1[roff + 2 * q + 1];
            }
            sGT[24 * 204 + j] = fast_tanh(acc24) + h1[roff + 24];
        }
        __syncthreads();
        if (tid < 100) {
            int d = tid / 25, mq = tid % 25;
            const ulonglong2* rg = (const ulonglong2*)(sRiT + d * 204);
            const ulonglong2* gg = (const ulonglong2*)(sGT + mq * 204);
            ull accp = pack2(0.0f, 0.0f);
            #pragma unroll 5
            for (int q = 0; q < 50; q++) {
                ulonglong2 rv = rg[q];
                ulonglong2 gv = gg[q];
                accp = ffma2(rv.x, gv.x, accp);
                accp = ffma2(rv.y, gv.y, accp);
            }
            float lo, hi;
            unpack2(accp, lo, hi);
            sXYZ[d * 100 + c * 25 + mq] = (lo + hi) * (1.0f / 200.0f);
        }
        __syncthreads();
    }

    // DR[m][q] = sum_d xyz[d][m] * xyz[d][q], q < 16
    for (int idx = tid; idx < 1600; idx += ETHR) {
        int m = idx >> 4, q = idx & 15;
        float s = 0.0f;
        #pragma unroll
        for (int d = 0; d < 4; d++)
            s += sXYZ[d * 100 + m] * sXYZ[d * 100 + q];
        g_DR[(size_t)a * 1600 + idx] = s;
    }
}

// ---------------------------------------------------------------------------
// Kernel 2: fitting net, f32x2 over row pairs (R4 structure).
// Block = 16 rows (4 n x 4 b). Shared 133120 B.
// ---------------------------------------------------------------------------
__global__ void __launch_bounds__(256, 1) fit_kernel(
    const int*   __restrict__ tmap,
    const float* __restrict__ fW0, const float* __restrict__ fb0,
    const float* __restrict__ fW1, const float* __restrict__ fb1,
    const float* __restrict__ fW2, const float* __restrict__ fb2,
    const float* __restrict__ fWf, const float* __restrict__ fbf,
    float* __restrict__ out)
{
    extern __shared__ float sm[];
    float* sDR2 = sm;            // pair p: [p*3200 + 2k + parity]
    float* sHa2 = sm + 25600;    // pair p: [p*480 + 2k + parity]
    float* sHb2 = sm + 29440;

    int tid = threadIdx.x;
    int g = blockIdx.x;
    int nn[4];
    nn[0] = g_sorted_n[g * 4 + 0];
    nn[1] = g_sorted_n[g * 4 + 1];
    nn[2] = g_sorted_n[g * 4 + 2];
    nn[3] = g_sorted_n[g * 4 + 3];
    int firstn = (nn[0] >= 0) ? nn[0] : (nn[1] >= 0) ? nn[1]
               : (nn[2] >= 0) ? nn[2] : nn[3];
    if (firstn < 0) return;
    int t = tmap[firstn];

    for (int idx = tid; idx < 16 * 1600; idx += 256) {
        int row = idx / 1600;
        int k   = idx - row * 1600;
        int b   = row >> 2, s = row & 3;
        int nv  = nn[s];
        float v = (nv >= 0) ? g_DR[((size_t)(b * 1024 + nv)) * 1600 + k] : 0.0f;
        sDR2[(row >> 1) * 3200 + 2 * k + (row & 1)] = v;
    }
    __syncthreads();

    int m = tid;
    const float* W0 = fW0 + (size_t)t * 1600 * 240;
    const float* W1 = fW1 + t * 240 * 240;
    const float* W2 = fW2 + t * 240 * 240;

    ull  accp[8];
    float prevA[16];
    float prevB[16];

    // layer0: 1600 -> 240
    if (m < 240) {
        float b0v = fb0[t * 240 + m];
        ull b0p = pack2(b0v, b0v);
        #pragma unroll
        for (int p = 0; p < 8; p++) accp[p] = b0p;
        for (int k = 0; k < 1600; k += 4) {
            float w0 = W0[(k + 0) * 240 + m];
            float w1 = W0[(k + 1) * 240 + m];
            float w2v = W0[(k + 2) * 240 + m];
            float w3 = W0[(k + 3) * 240 + m];
            ull wp0 = pack2(w0, w0), wp1 = pack2(w1, w1);
            ull wp2 = pack2(w2v, w2v), wp3 = pack2(w3, w3);
            #pragma unroll
            for (int p = 0; p < 8; p++) {
                const ulonglong2* dd = (const ulonglong2*)(sDR2 + p * 3200 + 2 * k);
                ulonglong2 dA = dd[0];
                ulonglong2 dB = dd[1];
                accp[p] = ffma2(dA.x, wp0, accp[p]);
                accp[p] = ffma2(dA.y, wp1, accp[p]);
                accp[p] = ffma2(dB.x, wp2, accp[p]);
                accp[p] = ffma2(dB.y, wp3, accp[p]);
            }
        }
        #pragma unroll
        for (int p = 0; p < 8; p++) {
            float lo, hi;
            unpack2(accp[p], lo, hi);
            float a0 = fast_tanh(lo), a1 = fast_tanh(hi);
            prevA[2 * p] = a0; prevA[2 * p + 1] = a1;
            *(ull*)(sHa2 + p * 480 + 2 * m) = pack2(a0, a1);
        }
    }
    __syncthreads();

    // layer1: 240 -> 240, resnet
    if (m < 240) {
        float b1v = fb1[t * 240 + m];
        ull b1p = pack2(b1v, b1v);
        #pragma unroll
        for (int p = 0; p < 8; p++) accp[p] = b1p;
        for (int k = 0; k < 240; k += 4) {
            float w0 = W1[(k + 0) * 240 + m];
            float w1 = W1[(k + 1) * 240 + m];
            float w2v = W1[(k + 2) * 240 + m];
            float w3 = W1[(k + 3) * 240 + m];
            ull wp0 = pack2(w0, w0), wp1 = pack2(w1, w1);
            ull wp2 = pack2(w2v, w2v), wp3 = pack2(w3, w3);
            #pragma unroll
            for (int p = 0; p < 8; p++) {
                const ulonglong2* hh = (const ulonglong2*)(sHa2 + p * 480 + 2 * k);
                ulonglong2 hA = hh[0];
                ulonglong2 hB = hh[1];
                accp[p] = ffma2(hA.x, wp0, accp[p]);
                accp[p] = ffma2(hA.y, wp1, accp[p]);
                accp[p] = ffma2(hB.x, wp2, accp[p]);
                accp[p] = ffma2(hB.y, wp3, accp[p]);
            }
        }
        #pragma unroll
        for (int p = 0; p < 8; p++) {
            float lo, hi;
            unpack2(accp[p], lo, hi);
            float a0 = fast_tanh(lo) + prevA[2 * p];
            float a1 = fast_tanh(hi) + prevA[2 * p + 1];
            prevB[2 * p] = a0; prevB[2 * p + 1] = a1;
            *(ull*)(sHb2 + p * 480 + 2 * m) = pack2(a0, a1);
        }
    }
    __syncthreads();

    // layer2: 240 -> 240, resnet; result into sHa2 (its reads are done)
    if (m < 240) {
        float b2v = fb2[t * 240 + m];
        ull b2p = pack2(b2v, b2v);
        #pragma unroll
        for (int p = 0; p < 8; p++) accp[p] = b2p;
        for (int k = 0; k < 240; k += 4) {
            float w0 = W2[(k + 0) * 240 + m];
            float w1 = W2[(k + 1) * 240 + m];
            float w2v = W2[(k + 2) * 240 + m];
            float w3 = W2[(k + 3) * 240 + m];
            ull wp0 = pack2(w0, w0), wp1 = pack2(w1, w1);
            ull wp2 = pack2(w2v, w2v), wp3 = pack2(w3, w3);
            #pragma unroll
            for (int p = 0; p < 8; p++) {
                const ulonglong2* hh = (const ulonglong2*)(sHb2 + p * 480 + 2 * k);
                ulonglong2 hA = hh[0];
                ulonglong2 hB = hh[1];
                accp[p] = ffma2(hA.x, wp0, accp[p]);
                accp[p] = ffma2(hA.y, wp1, accp[p]);
                accp[p] = ffma2(hB.x, wp2, accp[p]);
                accp[p] = ffma2(hB.y, wp3, accp[p]);
            }
        }
        #pragma unroll
        for (int p = 0; p < 8; p++) {
            float lo, hi;
            unpack2(accp[p], lo, hi);
            float a0 = fast_tanh(lo) + prevB[2 * p];
            float a1 = fast_tanh(hi) + prevB[2 * p + 1];
            *(ull*)(sHa2 + p * 480 + 2 * m) = pack2(a0, a1);
        }
    }
    __syncthreads();

    // final: h @ fWf + fbf
    if (tid < 16) {
        int i = tid, b = i >> 2, s = i & 3;
        int nv = nn[s];
        if (nv >= 0) {
            int p = i >> 1, par = i & 1;
            float e = fbf[t];
            const float* Wf = fWf + t * 240;
            float s0 = 0.0f;
            for (int k = 0; k < 240; k++)
                s0 += sHa2[p * 480 + 2 * k + par] * Wf[k];
            out[4 + b * 1024 + nv] = e + s0;
        }
    }
}

// ---------------------------------------------------------------------------
// Kernel 3: Etot = sum_n Ei (deterministic tree reduce, one block per batch)
// ---------------------------------------------------------------------------
__global__ void etot_kernel(float* __restrict__ out)
{
    __shared__ float red[256];
    int b = blockIdx.x, tid = threadIdx.x;
    float s = 0.0f;
    for (int i = tid; i < 1024; i += 256) s += out[4 + b * 1024 + i];
    red[tid] = s;
    __syncthreads();
    for (int off = 128; off > 0; off >>= 1) {
        if (tid < off) red[tid] += red[tid + off];
        __syncthreads();
    }
    if (tid == 0) out[b] = red[0];
}

// ---------------------------------------------------------------------------
extern "C" void kernel_launch(void* const* d_in, const int* in_sizes, int n_in,
                              void* d_out, int out_size)
{
    int off = (n_in >= 24) ? 0 : -1;   // nghost scalar may or may not materialize

    const int*    tmap = (const int*)   d_in[1];
    const float4* imdr = (const float4*)d_in[3];
    const float4* davg = (const float4*)d_in[5 + off];
    const float4* dstd = (const float4*)d_in[6 + off];
    const float*  tvec = (const float*) d_in[7 + off];
    const float*  tW0  = (const float*) d_in[8 + off];
    const float*  tb0  = (const float*) d_in[9 + off];
    const float*  eW0  = (const float*) d_in[10 + off];
    const float*  eb0  = (const float*) d_in[11 + off];
    const float*  eW1  = (const float*) d_in[12 + off];
    const float*  eb1  = (const float*) d_in[13 + off];
    const float*  eW2  = (const float*) d_in[14 + off];
    const float*  eb2  = (const float*) d_in[15 + off];
    const float*  fW0  = (const float*) d_in[16 + off];
    const float*  fb0  = (const float*) d_in[17 + off];
    const float*  fW1  = (const float*) d_in[18 + off];
    const float*  fb1  = (const float*) d_in[19 + off];
    const float*  fW2  = (const float*) d_in[20 + off];
    const float*  fb2  = (const float*) d_in[21 + off];
    const float*  fWf  = (const float*) d_in[22 + off];
    const float*  fbf  = (const float*) d_in[23 + off];
    float* out = (float*)d_out;

    cudaFuncSetAttribute(embed_kernel, cudaFuncAttributeMaxDynamicSharedMemorySize, 54752);
    cudaFuncSetAttribute(fit_kernel,   cudaFuncAttributeMaxDynamicSharedMemorySize, 133120);

    sort_kernel<<<1, 1024>>>(tmap);
    embed_kernel<<<4096, ETHR, 54752>>>(imdr, tmap, davg, dstd, tvec,
                                        tW0, tb0, eW0, eb0, eW1, eb1, eW2, eb2);
    fit_kernel<<<258, 256, 133120>>>(tmap, fW0, fb0, fW1, fb1, fW2, fb2,
                                     fWf, fbf, out);
    etot_kernel<<<4, 256>>>(out);
}

// round 11
// speedup vs baseline: 2.3393x; 2.3393x over previous
#include <cuda_runtime.h>
#include <math.h>

#define BB    4
#define NATN  1024
#define K_TAB 16384
#define S_LO  (-2.0f)
#define S_HI  (12.0f)

typedef unsigned long long ull;

// scratch: DR descriptors, G-table, type-sorted atom list
__device__ float g_DR[(size_t)BB * NATN * 1600];
__device__ float g_tab[2 * K_TAB * 100];       // 13.1 MB, [nt][knot][m]
__device__ int   g_sorted_n[1032];

// ---------------- packed f32x2 helpers (SASS FFMA2) ----------------
__device__ __forceinline__ ull pack2(float lo, float hi)
{
    ull r;
    asm("mov.b64 %0, {%1, %2};" : "=l"(r) : "f"(lo), "f"(hi));
    return r;
}
__device__ __forceinline__ void unpack2(ull v, float& lo, float& hi)
{
    asm("mov.b64 {%0, %1}, %2;" : "=f"(lo), "=f"(hi) : "l"(v));
}
__device__ __forceinline__ ull ffma2(ull a, ull b, ull c)
{
    ull d;
    asm("fma.rn.f32x2 %0, %1, %2, %3;" : "=l"(d) : "l"(a), "l"(b), "l"(c));
    return d;
}

// Exact-path lean tanh: 1 - 2*rcp(exp(2x)+1). Rel err ~1e-6, branch-free.
__device__ __forceinline__ float fast_tanh(float x)
{
    float e = __expf(2.0f * x);
    float r;
    asm("rcp.approx.f32 %0, %1;" : "=f"(r) : "f"(e + 1.0f));
    return fmaf(-2.0f, r, 1.0f);
}

// ---------------------------------------------------------------------------
// Kernel 0: deterministic partition of n-indices by atom type (single block)
// ---------------------------------------------------------------------------
__global__ void sort_kernel(const int* __restrict__ tmap)
{
    __shared__ int sa[1024], sb[1024];
    int tid = threadIdx.x;
    int myt = tmap[tid];
    sa[tid] = (myt == 0) ? 1 : 0;
    __syncthreads();
    int* cur = sa; int* nxt = sb;
    for (int off = 1; off < 1024; off <<= 1) {
        int v = cur[tid];
        if (tid >= off) v += cur[tid - off];
        __syncthreads();
        nxt[tid] = v;
        __syncthreads();
        int* tpp = cur; cur = nxt; nxt = tpp;
    }
    int scan0 = cur[tid];
    int cnt0  = cur[1023];

    g_sorted_n[tid] = -1;
    if (tid < 8) g_sorted_n[1024 + tid] = -1;
    __syncthreads();

    if (myt == 0) {
        g_sorted_n[scan0 - 1] = tid;
    } else {
        int base1 = ((cnt0 + 3) >> 2) << 2;
        g_sorted_n[base1 + tid - scan0] = tid;
    }
}

// ---------------------------------------------------------------------------
// Kernel 1: build G-table. G_nt(s) = embedding-MLP(concat[s, nf_nt]).
// nt = NEIGHBOR type. One thread per (nt, knot). Exact MLP math.
// ---------------------------------------------------------------------------
__global__ void __launch_bounds__(256) build_tab_kernel(
    const float* __restrict__ tvec,
    const float* __restrict__ tW0, const float* __restrict__ tb0,
    const float* __restrict__ eW0, const float* __restrict__ eb0,
    const float* __restrict__ eW1, const float* __restrict__ eb1,
    const float* __restrict__ eW2, const float* __restrict__ eb2)
{
    __shared__ float sW1[1250], sB1[50], sW2[5000], sBias[50], sW0c[25], sB2[100];
    int tid = threadIdx.x;

    for (int i = tid; i < 1250; i += 256) sW1[i] = eW1[i];
    for (int i = tid; i < 50;   i += 256) sB1[i] = eb1[i];
    for (int i = tid; i < 5000; i += 256) sW2[i] = eW2[i];
    for (int i = tid; i < 100;  i += 256) sB2[i] = eb2[i];
    for (int i = tid; i < 25;   i += 256) sW0c[i] = eW0[i];   // eW0 row 0 (s coeff)

    if (tid < 50) {
        // folded layer0 bias: sBias[nt][m] = eb0[m] + sum_k nf_nt[k]*eW0[1+k][m]
        int tt = tid / 25, m = tid % 25;
        float tv[4];
        #pragma unroll
        for (int p = 0; p < 4; p++) tv[p] = tvec[tt * 4 + p];
        float bias = eb0[m];
        #pragma unroll
        for (int k = 0; k < 8; k++) {
            float acc = tb0[k];
            #pragma unroll
            for (int p = 0; p < 4; p++) acc += tv[p] * tW0[p * 8 + k];
            float nfk = fast_tanh(acc) + tv[k & 3];
            bias += nfk * eW0[(k + 1) * 25 + m];
        }
        sBias[tt * 25 + m] = bias;
    }
    __syncthreads();

    int idx = blockIdx.x * 256 + tid;       // 0 .. 2*K_TAB-1
    int t = idx >> 14;                      // K_TAB = 2^14
    int i = idx & (K_TAB - 1);
    float s = S_LO + (S_HI - S_LO) * ((float)i / (float)(K_TAB - 1));

    // layer0: 1 scalar input + folded bias -> 25
    float h0[25];
    #pragma unroll
    for (int m = 0; m < 25; m++)
        h0[m] = fast_tanh(sBias[t * 25 + m] + s * sW0c[m]);

    // layer1: 25 -> 50, resnet concat[h0,h0]
    float h1[50];
    #pragma unroll
    for (int m = 0; m < 50; m++) h1[m] = sB1[m];
    for (int k = 0; k < 25; k++) {
        float hk = h0[k];
        #pragma unroll
        for (int m = 0; m < 50; m++) h1[m] += hk * sW1[k * 50 + m];
    }
    #pragma unroll
    for (int m = 0; m < 50; m++)
        h1[m] = fast_tanh(h1[m]) + h0[(m < 25) ? m : (m - 25)];

    // layer2: 50 -> 100, resnet concat[h1,h1]; two 50-wide chunks
    float* out = g_tab + (size_t)(t * K_TAB + i) * 100;
    for (int c = 0; c < 2; c++) {
        float acc[50];
        #pragma unroll
        for (int m = 0; m < 50; m++) acc[m] = sB2[c * 50 + m];
        for (int k = 0; k < 50; k++) {
            float hk = h1[k];
            #pragma unroll
            for (int m = 0; m < 50; m++) acc[m] += hk * sW2[k * 100 + c * 50 + m];
        }
        // resnet index (c*50+m) mod 50 == m for both chunks
        #pragma unroll
        for (int m = 0; m < 50; m++)
            out[c * 50 + m] = fast_tanh(acc[m]) + h1[m];
    }
}

// ---------------------------------------------------------------------------
// Kernel 2: embed via table interpolation + xyz + DR. One block = atom.
// Phase 2 thread = (j-half, m). j-half IS the neighbor type (j<100 -> nt=0,
// j>=100 -> nt=1), so the table base uses jh — NOT the center-atom type
// (that was the R10 bug). Center type t is only for davg/dstd.
// ---------------------------------------------------------------------------
__global__ void __launch_bounds__(256) embed_kernel(
    const float4* __restrict__ imdr,
    const int*    __restrict__ tmap,
    const float4* __restrict__ davg,
    const float4* __restrict__ dstd)
{
    __shared__ int    sK[200];      // knot*100 (pre-scaled row offset)
    __shared__ float  sF[200];      // fraction
    __shared__ float4 sRi4[200];
    __shared__ float  sP[1024];     // partials: [jh][d][128]
    __shared__ float  sXYZ[400];

    int tid = threadIdx.x;
    int a = blockIdx.x;
    int n = a & 1023;
    int t = tmap[n];

    if (tid < 200) {
        int j = tid;
        float4 im = imdr[(size_t)a * 200 + j];
        float r = im.x;
        float invr = (r > 1e-5f) ? (1.0f / r) : 1.0f;
        float u  = (r - 0.5f) * (1.0f / 5.5f);
        float u2 = u * u;
        float smid = invr * (u * u2 * (-6.0f * u2 + 15.0f * u - 10.0f) + 1.0f);
        float srij = 0.0f;
        if (r > 0.0f && r < 0.5f)        srij = invr;
        else if (r >= 0.5f && r < 6.0f)  srij = smid;
        bool msk = fabsf(r) > 1e-5f;
        float v0 = srij;
        float v1 = msk ? srij * im.y * invr : 0.0f;
        float v2 = msk ? srij * im.z * invr : 0.0f;
        float v3 = msk ? srij * im.w * invr : 0.0f;
        float4 da = davg[t * 200 + j];
        float4 ds = dstd[t * 200 + j];
        v0 = (v0 - da.x) / ds.x;
        v1 = (v1 - da.y) / ds.y;
        v2 = (v2 - da.z) / ds.z;
        v3 = (v3 - da.w) / ds.w;
        sRi4[j] = make_float4(v0, v1, v2, v3);

        // table position: v0 IS the MLP scalar input
        float pos = (v0 - S_LO) * ((float)(K_TAB - 1) / (S_HI - S_LO));
        pos = fminf(fmaxf(pos, 0.0f), (float)(K_TAB - 1));
        float kf = floorf(pos);
        int k = (int)kf;
        if (k > K_TAB - 2) k = K_TAB - 2;
        sK[j] = k * 100;
        sF[j] = pos - (float)k;
    }
    __syncthreads();

    // Phase 2: xyz[d][m] = sum_j Ri[j][d] * G_nt(j)[m]; j split into 2 halves,
    // half index jh == neighbor type nt.
    int jh = tid >> 7;
    int mslot = tid & 127;
    if (mslot < 100) {
        const float* tb = g_tab + (size_t)jh * K_TAB * 100 + mslot;  // nt = jh
        int j0 = jh * 100;
        float a0 = 0.0f, a1 = 0.0f, a2 = 0.0f, a3 = 0.0f;
        #pragma unroll 4
        for (int jj = 0; jj < 100; jj++) {
            int j = j0 + jj;
            int ko = sK[j];
            float f = sF[j];
            float4 ri = sRi4[j];
            float t0 = __ldg(tb + ko);
            float t1 = __ldg(tb + ko + 100);
            float g = fmaf(f, t1 - t0, t0);
            a0 = fmaf(ri.x, g, a0);
            a1 = fmaf(ri.y, g, a1);
            a2 = fmaf(ri.z, g, a2);
            a3 = fmaf(ri.w, g, a3);
        }
        sP[jh * 512 +   0 + mslot] = a0;
        sP[jh * 512 + 128 + mslot] = a1;
        sP[jh * 512 + 256 + mslot] = a2;
        sP[jh * 512 + 384 + mslot] = a3;
    }
    __syncthreads();

    // combine halves (strided loop — 400 outputs, 256 threads)
    for (int i = tid; i < 400; i += 256) {
        int d = i / 100, m = i - d * 100;
        sXYZ[d * 100 + m] =
            (sP[d * 128 + m] + sP[512 + d * 128 + m]) * (1.0f / 200.0f);
    }
    __syncthreads();

    // DR[m][q] = sum_d xyz[d][m] * xyz[d][q], q < 16
    for (int idx = tid; idx < 1600; idx += 256) {
        int m = idx >> 4, q = idx & 15;
        float s = 0.0f;
        #pragma unroll
        for (int d = 0; d < 4; d++)
            s += sXYZ[d * 100 + m] * sXYZ[d * 100 + q];
        g_DR[(size_t)a * 1600 + idx] = s;
    }
}

// ---------------------------------------------------------------------------
// Kernel 3: fitting net, f32x2 over row pairs (proven R4/R8 structure).
// Block = 16 rows (4 n x 4 b). Shared 133120 B.
// ---------------------------------------------------------------------------
__global__ void __launch_bounds__(256, 1) fit_kernel(
    const int*   __restrict__ tmap,
    const float* __restrict__ fW0, const float* __restrict__ fb0,
    const float* __restrict__ fW1, const float* __restrict__ fb1,
    const float* __restrict__ fW2, const float* __restrict__ fb2,
    const float* __restrict__ fWf, const float* __restrict__ fbf,
    float* __restrict__ out)
{
    extern __shared__ float sm[];
    float* sDR2 = sm;            // pair p: [p*3200 + 2k + parity]
    float* sHa2 = sm + 25600;    // pair p: [p*480 + 2k + parity]
    float* sHb2 = sm + 29440;

    int tid = threadIdx.x;
    int g = blockIdx.x;
    int nn[4];
    nn[0] = g_sorted_n[g * 4 + 0];
    nn[1] = g_sorted_n[g * 4 + 1];
    nn[2] = g_sorted_n[g * 4 + 2];
    nn[3] = g_sorted_n[g * 4 + 3];
    int firstn = (nn[0] >= 0) ? nn[0] : (nn[1] >= 0) ? nn[1]
               : (nn[2] >= 0) ? nn[2] : nn[3];
    if (firstn < 0) return;
    int t = tmap[firstn];

    for (int idx = tid; idx < 16 * 1600; idx += 256) {
        int row = idx / 1600;
        int k   = idx - row * 1600;
        int b   = row >> 2, s = row & 3;
        int nv  = nn[s];
        float v = (nv >= 0) ? g_DR[((size_t)(b * 1024 + nv)) * 1600 + k] : 0.0f;
        sDR2[(row >> 1) * 3200 + 2 * k + (row & 1)] = v;
    }
    __syncthreads();

    int m = tid;
    const float* W0 = fW0 + (size_t)t * 1600 * 240;
    const float* W1 = fW1 + t * 240 * 240;
    const float* W2 = fW2 + t * 240 * 240;

    ull  accp[8];
    float prevA[16];
    float prevB[16];

    // layer0: 1600 -> 240
    if (m < 240) {
        float b0v = fb0[t * 240 + m];
        ull b0p = pack2(b0v, b0v);
        #pragma unroll
        for (int p = 0; p < 8; p++) accp[p] = b0p;
        for (int k = 0; k < 1600; k += 4) {
            float w0 = W0[(k + 0) * 240 + m];
            float w1 = W0[(k + 1) * 240 + m];
            float w2v = W0[(k + 2) * 240 + m];
            float w3 = W0[(k + 3) * 240 + m];
            ull wp0 = pack2(w0, w0), wp1 = pack2(w1, w1);
            ull wp2 = pack2(w2v, w2v), wp3 = pack2(w3, w3);
            #pragma unroll
            for (int p = 0; p < 8; p++) {
                const ulonglong2* dd = (const ulonglong2*)(sDR2 + p * 3200 + 2 * k);
                ulonglong2 dA = dd[0];
                ulonglong2 dB = dd[1];
                accp[p] = ffma2(dA.x, wp0, accp[p]);
                accp[p] = ffma2(dA.y, wp1, accp[p]);
                accp[p] = ffma2(dB.x, wp2, accp[p]);
                accp[p] = ffma2(dB.y, wp3, accp[p]);
            }
        }
        #pragma unroll
        for (int p = 0; p < 8; p++) {
            float lo, hi;
            unpack2(accp[p], lo, hi);
            float a0 = fast_tanh(lo), a1 = fast_tanh(hi);
            prevA[2 * p] = a0; prevA[2 * p + 1] = a1;
            *(ull*)(sHa2 + p * 480 + 2 * m) = pack2(a0, a1);
        }
    }
    __syncthreads();

    // layer1: 240 -> 240, resnet
    if (m < 240) {
        float b1v = fb1[t * 240 + m];
        ull b1p = pack2(b1v, b1v);
        #pragma unroll
        for (int p = 0; p < 8; p++) accp[p] = b1p;
        for (int k = 0; k < 240; k += 4) {
            float w0 = W1[(k + 0) * 240 + m];
            float w1 = W1[(k + 1) * 240 + m];
            float w2v = W1[(k + 2) * 240 + m];
            float w3 = W1[(k + 3) * 240 + m];
            ull wp0 = pack2(w0, w0), wp1 = pack2(w1, w1);
            ull wp2 = pack2(w2v, w2v), wp3 = pack2(w3, w3);
            #pragma unroll
            for (int p = 0; p < 8; p++) {
                const ulonglong2* hh = (const ulonglong2*)(sHa2 + p * 480 + 2 * k);
                ulonglong2 hA = hh[0];
                ulonglong2 hB = hh[1];
                accp[p] = ffma2(hA.x, wp0, accp[p]);
                accp[p] = ffma2(hA.y, wp1, accp[p]);
                accp[p] = ffma2(hB.x, wp2, accp[p]);
                accp[p] = ffma2(hB.y, wp3, accp[p]);
            }
        }
        #pragma unroll
        for (int p = 0; p < 8; p++) {
            float lo, hi;
            unpack2(accp[p], lo, hi);
            float a0 = fast_tanh(lo) + prevA[2 * p];
            float a1 = fast_tanh(hi) + prevA[2 * p + 1];
            prevB[2 * p] = a0; prevB[2 * p + 1] = a1;
            *(ull*)(sHb2 + p * 480 + 2 * m) = pack2(a0, a1);
        }
    }
    __syncthreads();

    // layer2: 240 -> 240, resnet; result into sHa2 (its reads are done)
    if (m < 240) {
        float b2v = fb2[t * 240 + m];
        ull b2p = pack2(b2v, b2v);
        #pragma unroll
        for (int p = 0; p < 8; p++) accp[p] = b2p;
        for (int k = 0; k < 240; k += 4) {
            float w0 = W2[(k + 0) * 240 + m];
            float w1 = W2[(k + 1) * 240 + m];
            float w2v = W2[(k + 2) * 240 + m];
            float w3 = W2[(k + 3) * 240 + m];
            ull wp0 = pack2(w0, w0), wp1 = pack2(w1, w1);
            ull wp2 = pack2(w2v, w2v), wp3 = pack2(w3, w3);
            #pragma unroll
            for (int p = 0; p < 8; p++) {
                const ulonglong2* hh = (const ulonglong2*)(sHb2 + p * 480 + 2 * k);
                ulonglong2 hA = hh[0];
                ulonglong2 hB = hh[1];
                accp[p] = ffma2(hA.x, wp0, accp[p]);
                accp[p] = ffma2(hA.y, wp1, accp[p]);
                accp[p] = ffma2(hB.x, wp2, accp[p]);
                accp[p] = ffma2(hB.y, wp3, accp[p]);
            }
        }
        #pragma unroll
        for (int p = 0; p < 8; p++) {
            float lo, hi;
            unpack2(accp[p], lo, hi);
            float a0 = fast_tanh(lo) + prevB[2 * p];
            float a1 = fast_tanh(hi) + prevB[2 * p + 1];
            *(ull*)(sHa2 + p * 480 + 2 * m) = pack2(a0, a1);
        }
    }
    __syncthreads();

    // final: h @ fWf + fbf
    if (tid < 16) {
        int i = tid, b = i >> 2, s = i & 3;
        int nv = nn[s];
        if (nv >= 0) {
            int p = i >> 1, par = i & 1;
            float e = fbf[t];
            const float* Wf = fWf + t * 240;
            float s0 = 0.0f;
            for (int k = 0; k < 240; k++)
                s0 += sHa2[p * 480 + 2 * k + par] * Wf[k];
            out[4 + b * 1024 + nv] = e + s0;
        }
    }
}

// ---------------------------------------------------------------------------
// Kernel 4: Etot = sum_n Ei (deterministic tree reduce, one block per batch)
// ---------------------------------------------------------------------------
__global__ void etot_kernel(float* __restrict__ out)
{
    __shared__ float red[256];
    int b = blockIdx.x, tid = threadIdx.x;
    float s = 0.0f;
    for (int i = tid; i < 1024; i += 256) s += out[4 + b * 1024 + i];
    red[tid] = s;
    __syncthreads();
    for (int off = 128; off > 0; off >>= 1) {
        if (tid < off) red[tid] += red[tid + off];
        __syncthreads();
    }
    if (tid == 0) out[b] = red[0];
}

// ---------------------------------------------------------------------------
extern "C" void kernel_launch(void* const* d_in, const int* in_sizes, int n_in,
                              void* d_out, int out_size)
{
    int off = (n_in >= 24) ? 0 : -1;   // nghost scalar may or may not materialize

    const int*    tmap = (const int*)   d_in[1];
    const float4* imdr = (const float4*)d_in[3];
    const float4* davg = (const float4*)d_in[5 + off];
    const float4* dstd = (const float4*)d_in[6 + off];
    const float*  tvec = (const float*) d_in[7 + off];
    const float*  tW0  = (const float*) d_in[8 + off];
    const float*  tb0  = (const float*) d_in[9 + off];
    const float*  eW0  = (const float*) d_in[10 + off];
    const float*  eb0  = (const float*) d_in[11 + off];
    const float*  eW1  = (const float*) d_in[12 + off];
    const float*  eb1  = (const float*) d_in[13 + off];
    const float*  eW2  = (const float*) d_in[14 + off];
    const float*  eb2  = (const float*) d_in[15 + off];
    const float*  fW0  = (const float*) d_in[16 + off];
    const float*  fb0  = (const float*) d_in[17 + off];
    const float*  fW1  = (const float*) d_in[18 + off];
    const float*  fb1  = (const float*) d_in[19 + off];
    const float*  fW2  = (const float*) d_in[20 + off];
    const float*  fb2  = (const float*) d_in[21 + off];
    const float*  fWf  = (const float*) d_in[22 + off];
    const float*  fbf  = (const float*) d_in[23 + off];
    float* out = (float*)d_out;

    cudaFuncSetAttribute(fit_kernel, cudaFuncAttributeMaxDynamicSharedMemorySize, 133120);

    sort_kernel<<<1, 1024>>>(tmap);
    build_tab_kernel<<<2 * K_TAB / 256, 256>>>(tvec, tW0, tb0, eW0, eb0,
                                               eW1, eb1, eW2, eb2);
    embed_kernel<<<4096, 256>>>(imdr, tmap, davg, dstd);
    fit_kernel<<<258, 256, 133120>>>(tmap, fW0, fb0, fW1, fb1, fW2, fb2,
                                     fWf, fbf, out);
    etot_kernel<<<4, 256>>>(out);
}

// round 12
// speedup vs baseline: 2.3716x; 1.0138x over previous
#include <cuda_runtime.h>
#include <math.h>

#define BB    4
#define NATN  1024
#define K_TAB 16384
#define S_LO  (-2.0f)
#define S_HI  (12.0f)

typedef unsigned long long ull;

// scratch: DR descriptors, G-table, type-sorted atom list
__device__ float g_DR[(size_t)BB * NATN * 1600];
__device__ float g_tab[2 * K_TAB * 100];       // 13.1 MB, [nt][knot][m]
__device__ int   g_sorted_n[1032];

// ---------------- packed f32x2 helpers (SASS FFMA2) ----------------
__device__ __forceinline__ ull pack2(float lo, float hi)
{
    ull r;
    asm("mov.b64 %0, {%1, %2};" : "=l"(r) : "f"(lo), "f"(hi));
    return r;
}
__device__ __forceinline__ void unpack2(ull v, float& lo, float& hi)
{
    asm("mov.b64 {%0, %1}, %2;" : "=f"(lo), "=f"(hi) : "l"(v));
}
__device__ __forceinline__ ull ffma2(ull a, ull b, ull c)
{
    ull d;
    asm("fma.rn.f32x2 %0, %1, %2, %3;" : "=l"(d) : "l"(a), "l"(b), "l"(c));
    return d;
}

// Exact-path lean tanh: 1 - 2*rcp(exp(2x)+1). Rel err ~1e-6, branch-free.
__device__ __forceinline__ float fast_tanh(float x)
{
    float e = __expf(2.0f * x);
    float r;
    asm("rcp.approx.f32 %0, %1;" : "=f"(r) : "f"(e + 1.0f));
    return fmaf(-2.0f, r, 1.0f);
}

// ---------------------------------------------------------------------------
// Kernel 0: deterministic partition of n-indices by atom type (single block)
// ---------------------------------------------------------------------------
__global__ void sort_kernel(const int* __restrict__ tmap)
{
    __shared__ int sa[1024], sb[1024];
    int tid = threadIdx.x;
    int myt = tmap[tid];
    sa[tid] = (myt == 0) ? 1 : 0;
    __syncthreads();
    int* cur = sa; int* nxt = sb;
    for (int off = 1; off < 1024; off <<= 1) {
        int v = cur[tid];
        if (tid >= off) v += cur[tid - off];
        __syncthreads();
        nxt[tid] = v;
        __syncthreads();
        int* tpp = cur; cur = nxt; nxt = tpp;
    }
    int scan0 = cur[tid];
    int cnt0  = cur[1023];

    g_sorted_n[tid] = -1;
    if (tid < 8) g_sorted_n[1024 + tid] = -1;
    __syncthreads();

    if (myt == 0) {
        g_sorted_n[scan0 - 1] = tid;
    } else {
        int base1 = ((cnt0 + 3) >> 2) << 2;
        g_sorted_n[base1 + tid - scan0] = tid;
    }
}

// ---------------------------------------------------------------------------
// Kernel 1: build G-table. G_nt(s) = embedding-MLP(concat[s, nf_nt]).
// nt = NEIGHBOR type. One thread per (nt, knot). Exact MLP math.
// ---------------------------------------------------------------------------
__global__ void __launch_bounds__(256) build_tab_kernel(
    const float* __restrict__ tvec,
    const float* __restrict__ tW0, const float* __restrict__ tb0,
    const float* __restrict__ eW0, const float* __restrict__ eb0,
    const float* __restrict__ eW1, const float* __restrict__ eb1,
    const float* __restrict__ eW2, const float* __restrict__ eb2)
{
    __shared__ float sW1[1250], sB1[50], sW2[5000], sBias[50], sW0c[25], sB2[100];
    int tid = threadIdx.x;

    for (int i = tid; i < 1250; i += 256) sW1[i] = eW1[i];
    for (int i = tid; i < 50;   i += 256) sB1[i] = eb1[i];
    for (int i = tid; i < 5000; i += 256) sW2[i] = eW2[i];
    for (int i = tid; i < 100;  i += 256) sB2[i] = eb2[i];
    for (int i = tid; i < 25;   i += 256) sW0c[i] = eW0[i];   // eW0 row 0 (s coeff)

    if (tid < 50) {
        // folded layer0 bias: sBias[nt][m] = eb0[m] + sum_k nf_nt[k]*eW0[1+k][m]
        int tt = tid / 25, m = tid % 25;
        float tv[4];
        #pragma unroll
        for (int p = 0; p < 4; p++) tv[p] = tvec[tt * 4 + p];
        float bias = eb0[m];
        #pragma unroll
        for (int k = 0; k < 8; k++) {
            float acc = tb0[k];
            #pragma unroll
            for (int p = 0; p < 4; p++) acc += tv[p] * tW0[p * 8 + k];
            float nfk = fast_tanh(acc) + tv[k & 3];
            bias += nfk * eW0[(k + 1) * 25 + m];
        }
        sBias[tt * 25 + m] = bias;
    }
    __syncthreads();

    int idx = blockIdx.x * 256 + tid;       // 0 .. 2*K_TAB-1
    int t = idx >> 14;                      // K_TAB = 2^14
    int i = idx & (K_TAB - 1);
    float s = S_LO + (S_HI - S_LO) * ((float)i / (float)(K_TAB - 1));

    // layer0: 1 scalar input + folded bias -> 25
    float h0[25];
    #pragma unroll
    for (int m = 0; m < 25; m++)
        h0[m] = fast_tanh(sBias[t * 25 + m] + s * sW0c[m]);

    // layer1: 25 -> 50, resnet concat[h0,h0]
    float h1[50];
    #pragma unroll
    for (int m = 0; m < 50; m++) h1[m] = sB1[m];
    for (int k = 0; k < 25; k++) {
        float hk = h0[k];
        #pragma unroll
        for (int m = 0; m < 50; m++) h1[m] += hk * sW1[k * 50 + m];
    }
    #pragma unroll
    for (int m = 0; m < 50; m++)
        h1[m] = fast_tanh(h1[m]) + h0[(m < 25) ? m : (m - 25)];

    // layer2: 50 -> 100, resnet concat[h1,h1]; two 50-wide chunks
    float* out = g_tab + (size_t)(t * K_TAB + i) * 100;
    for (int c = 0; c < 2; c++) {
        float acc[50];
        #pragma unroll
        for (int m = 0; m < 50; m++) acc[m] = sB2[c * 50 + m];
        for (int k = 0; k < 50; k++) {
            float hk = h1[k];
            #pragma unroll
            for (int m = 0; m < 50; m++) acc[m] += hk * sW2[k * 100 + c * 50 + m];
        }
        // resnet index (c*50+m) mod 50 == m for both chunks
        #pragma unroll
        for (int m = 0; m < 50; m++)
            out[c * 50 + m] = fast_tanh(acc[m]) + h1[m];
    }
}

// ---------------------------------------------------------------------------
// Kernel 2: embed via table interpolation + xyz + DR. One block = atom.
// Phase 2 thread = (j-half, m); j-half IS the neighbor type.
// ---------------------------------------------------------------------------
__global__ void __launch_bounds__(256) embed_kernel(
    const float4* __restrict__ imdr,
    const int*    __restrict__ tmap,
    const float4* __restrict__ davg,
    const float4* __restrict__ dstd)
{
    __shared__ int    sK[200];      // knot*100 (pre-scaled row offset)
    __shared__ float  sF[200];      // fraction
    __shared__ float4 sRi4[200];
    __shared__ float  sP[1024];     // partials: [jh][d][128]
    __shared__ float  sXYZ[400];

    int tid = threadIdx.x;
    int a = blockIdx.x;
    int n = a & 1023;
    int t = tmap[n];

    if (tid < 200) {
        int j = tid;
        float4 im = imdr[(size_t)a * 200 + j];
        float r = im.x;
        float invr = (r > 1e-5f) ? (1.0f / r) : 1.0f;
        float u  = (r - 0.5f) * (1.0f / 5.5f);
        float u2 = u * u;
        float smid = invr * (u * u2 * (-6.0f * u2 + 15.0f * u - 10.0f) + 1.0f);
        float srij = 0.0f;
        if (r > 0.0f && r < 0.5f)        srij = invr;
        else if (r >= 0.5f && r < 6.0f)  srij = smid;
        bool msk = fabsf(r) > 1e-5f;
        float v0 = srij;
        float v1 = msk ? srij * im.y * invr : 0.0f;
        float v2 = msk ? srij * im.z * invr : 0.0f;
        float v3 = msk ? srij * im.w * invr : 0.0f;
        float4 da = davg[t * 200 + j];
        float4 ds = dstd[t * 200 + j];
        v0 = (v0 - da.x) / ds.x;
        v1 = (v1 - da.y) / ds.y;
        v2 = (v2 - da.z) / ds.z;
        v3 = (v3 - da.w) / ds.w;
        sRi4[j] = make_float4(v0, v1, v2, v3);

        float pos = (v0 - S_LO) * ((float)(K_TAB - 1) / (S_HI - S_LO));
        pos = fminf(fmaxf(pos, 0.0f), (float)(K_TAB - 1));
        float kf = floorf(pos);
        int k = (int)kf;
        if (k > K_TAB - 2) k = K_TAB - 2;
        sK[j] = k * 100;
        sF[j] = pos - (float)k;
    }
    __syncthreads();

    // Phase 2: xyz[d][m] = sum_j Ri[j][d] * G_nt(j)[m]; nt == jh.
    int jh = tid >> 7;
    int mslot = tid & 127;
    if (mslot < 100) {
        const float* tb = g_tab + (size_t)jh * K_TAB * 100 + mslot;  // nt = jh
        int j0 = jh * 100;
        float a0 = 0.0f, a1 = 0.0f, a2 = 0.0f, a3 = 0.0f;
        #pragma unroll 4
        for (int jj = 0; jj < 100; jj++) {
            int j = j0 + jj;
            int ko = sK[j];
            float f = sF[j];
            float4 ri = sRi4[j];
            float t0 = __ldg(tb + ko);
            float t1 = __ldg(tb + ko + 100);
            float g = fmaf(f, t1 - t0, t0);
            a0 = fmaf(ri.x, g, a0);
            a1 = fmaf(ri.y, g, a1);
            a2 = fmaf(ri.z, g, a2);
            a3 = fmaf(ri.w, g, a3);
        }
        sP[jh * 512 +   0 + mslot] = a0;
        sP[jh * 512 + 128 + mslot] = a1;
        sP[jh * 512 + 256 + mslot] = a2;
        sP[jh * 512 + 384 + mslot] = a3;
    }
    __syncthreads();

    // combine halves (strided loop — 400 outputs, 256 threads)
    for (int i = tid; i < 400; i += 256) {
        int d = i / 100, m = i - d * 100;
        sXYZ[d * 100 + m] =
            (sP[d * 128 + m] + sP[512 + d * 128 + m]) * (1.0f / 200.0f);
    }
    __syncthreads();

    // DR[m][q] = sum_d xyz[d][m] * xyz[d][q], q < 16
    for (int idx = tid; idx < 1600; idx += 256) {
        int m = idx >> 4, q = idx & 15;
        float s = 0.0f;
        #pragma unroll
        for (int d = 0; d < 4; d++)
            s += sXYZ[d * 100 + m] * sXYZ[d * 100 + q];
        g_DR[(size_t)a * 1600 + idx] = s;
    }
}

// ---------------------------------------------------------------------------
// Kernel 3: fitting net, f32x2 over row pairs. Block = 8 rows
// (4 same-type n x 2 batches) -> smem 66560 B -> 2 CTAs/SM (16 warps,
// 2x the latency hiding of the 16-row version). Grid (258, 2).
// ---------------------------------------------------------------------------
__global__ void __launch_bounds__(256, 2) fit_kernel(
    const int*   __restrict__ tmap,
    const float* __restrict__ fW0, const float* __restrict__ fb0,
    const float* __restrict__ fW1, const float* __restrict__ fb1,
    const float* __restrict__ fW2, const float* __restrict__ fb2,
    const float* __restrict__ fWf, const float* __restrict__ fbf,
    float* __restrict__ out)
{
    extern __shared__ float sm[];
    float* sDR2 = sm;            // pair p(0..3): [p*3200 + 2k + parity]
    float* sHa2 = sm + 12800;    // pair p: [p*480 + 2k + parity]
    float* sHb2 = sm + 14720;
    // total 16640 floats = 66560 B

    int tid = threadIdx.x;
    int g  = blockIdx.x;
    int bp = blockIdx.y;         // batch pair: batches {2bp, 2bp+1}
    int nn[4];
    nn[0] = g_sorted_n[g * 4 + 0];
    nn[1] = g_sorted_n[g * 4 + 1];
    nn[2] = g_sorted_n[g * 4 + 2];
    nn[3] = g_sorted_n[g * 4 + 3];
    int firstn = (nn[0] >= 0) ? nn[0] : (nn[1] >= 0) ? nn[1]
               : (nn[2] >= 0) ? nn[2] : nn[3];
    if (firstn < 0) return;
    int t = tmap[firstn];

    // stage 8 rows of DR, row-pair interleaved.
    // row = lb*4 + s (lb in 0..1 -> batch 2bp+lb, s = n-slot), pair = row>>1.
    for (int idx = tid; idx < 8 * 1600; idx += 256) {
        int row = idx / 1600;
        int k   = idx - row * 1600;
        int lb  = row >> 2, s = row & 3;
        int nv  = nn[s];
        int b   = bp * 2 + lb;
        float v = (nv >= 0) ? g_DR[((size_t)(b * 1024 + nv)) * 1600 + k] : 0.0f;
        sDR2[(row >> 1) * 3200 + 2 * k + (row & 1)] = v;
    }
    __syncthreads();

    int m = tid;
    const float* W0 = fW0 + (size_t)t * 1600 * 240;
    const float* W1 = fW1 + t * 240 * 240;
    const float* W2 = fW2 + t * 240 * 240;

    ull  accp[4];
    float prevA[8];
    float prevB[8];

    // layer0: 1600 -> 240
    if (m < 240) {
        float b0v = fb0[t * 240 + m];
        ull b0p = pack2(b0v, b0v);
        #pragma unroll
        for (int p = 0; p < 4; p++) accp[p] = b0p;
        for (int k = 0; k < 1600; k += 4) {
            float w0 = W0[(k + 0) * 240 + m];
            float w1 = W0[(k + 1) * 240 + m];
            float w2v = W0[(k + 2) * 240 + m];
            float w3 = W0[(k + 3) * 240 + m];
            ull wp0 = pack2(w0, w0), wp1 = pack2(w1, w1);
            ull wp2 = pack2(w2v, w2v), wp3 = pack2(w3, w3);
            #pragma unroll
            for (int p = 0; p < 4; p++) {
                const ulonglong2* dd = (const ulonglong2*)(sDR2 + p * 3200 + 2 * k);
                ulonglong2 dA = dd[0];
                ulonglong2 dB = dd[1];
                accp[p] = ffma2(dA.x, wp0, accp[p]);
                accp[p] = ffma2(dA.y, wp1, accp[p]);
                accp[p] = ffma2(dB.x, wp2, accp[p]);
                accp[p] = ffma2(dB.y, wp3, accp[p]);
            }
        }
        #pragma unroll
        for (int p = 0; p < 4; p++) {
            float lo, hi;
            unpack2(accp[p], lo, hi);
            float a0 = fast_tanh(lo), a1 = fast_tanh(hi);
            prevA[2 * p] = a0; prevA[2 * p + 1] = a1;
            *(ull*)(sHa2 + p * 480 + 2 * m) = pack2(a0, a1);
        }
    }
    __syncthreads();

    // layer1: 240 -> 240, resnet
    if (m < 240) {
        float b1v = fb1[t * 240 + m];
        ull b1p = pack2(b1v, b1v);
        #pragma unroll
        for (int p = 0; p < 4; p++) accp[p] = b1p;
        for (int k = 0; k < 240; k += 4) {
            float w0 = W1[(k + 0) * 240 + m];
            float w1 = W1[(k + 1) * 240 + m];
            float w2v = W1[(k + 2) * 240 + m];
            float w3 = W1[(k + 3) * 240 + m];
            ull wp0 = pack2(w0, w0), wp1 = pack2(w1, w1);
            ull wp2 = pack2(w2v, w2v), wp3 = pack2(w3, w3);
            #pragma unroll
            for (int p = 0; p < 4; p++) {
                const ulonglong2* hh = (const ulonglong2*)(sHa2 + p * 480 + 2 * k);
                ulonglong2 hA = hh[0];
                ulonglong2 hB = hh[1];
                accp[p] = ffma2(hA.x, wp0, accp[p]);
                accp[p] = ffma2(hA.y, wp1, accp[p]);
                accp[p] = ffma2(hB.x, wp2, accp[p]);
                accp[p] = ffma2(hB.y, wp3, accp[p]);
            }
        }
        #pragma unroll
        for (int p = 0; p < 4; p++) {
            float lo, hi;
            unpack2(accp[p], lo, hi);
            float a0 = fast_tanh(lo) + prevA[2 * p];
            float a1 = fast_tanh(hi) + prevA[2 * p + 1];
            prevB[2 * p] = a0; prevB[2 * p + 1] = a1;
            *(ull*)(sHb2 + p * 480 + 2 * m) = pack2(a0, a1);
        }
    }
    __syncthreads();

    // layer2: 240 -> 240, resnet; result into sHa2 (its reads are done)
    if (m < 240) {
        float b2v = fb2[t * 240 + m];
        ull b2p = pack2(b2v, b2v);
        #pragma unroll
        for (int p = 0; p < 4; p++) accp[p] = b2p;
        for (int k = 0; k < 240; k += 4) {
            float w0 = W2[(k + 0) * 240 + m];
            float w1 = W2[(k + 1) * 240 + m];
            float w2v = W2[(k + 2) * 240 + m];
            float w3 = W2[(k + 3) * 240 + m];
            ull wp0 = pack2(w0, w0), wp1 = pack2(w1, w1);
            ull wp2 = pack2(w2v, w2v), wp3 = pack2(w3, w3);
            #pragma unroll
            for (int p = 0; p < 4; p++) {
                const ulonglong2* hh = (const ulonglong2*)(sHb2 + p * 480 + 2 * k);
                ulonglong2 hA = hh[0];
                ulonglong2 hB = hh[1];
                accp[p] = ffma2(hA.x, wp0, accp[p]);
                accp[p] = ffma2(hA.y, wp1, accp[p]);
                accp[p] = ffma2(hB.x, wp2, accp[p]);
                accp[p] = ffma2(hB.y, wp3, accp[p]);
            }
        }
        #pragma unroll
        for (int p = 0; p < 4; p++) {
            float lo, hi;
            unpack2(accp[p], lo, hi);
            float a0 = fast_tanh(lo) + prevB[2 * p];
            float a1 = fast_tanh(hi) + prevB[2 * p + 1];
            *(ull*)(sHa2 + p * 480 + 2 * m) = pack2(a0, a1);
        }
    }
    __syncthreads();

    // final: h @ fWf + fbf (8 rows)
    if (tid < 8) {
        int i = tid;
        int lb = i >> 2, s = i & 3;
        int nv = nn[s];
        if (nv >= 0) {
            int b = bp * 2 + lb;
            int p = i >> 1, par = i & 1;
            float e = fbf[t];
            const float* Wf = fWf + t * 240;
            float s0 = 0.0f;
            for (int k = 0; k < 240; k++)
                s0 += sHa2[p * 480 + 2 * k + par] * Wf[k];
            out[4 + b * 1024 + nv] = e + s0;
        }
    }
}

// ---------------------------------------------------------------------------
// Kernel 4: Etot = sum_n Ei (deterministic tree reduce, one block per batch)
// ---------------------------------------------------------------------------
__global__ void etot_kernel(float* __restrict__ out)
{
    __shared__ float red[256];
    int b = blockIdx.x, tid = threadIdx.x;
    float s = 0.0f;
    for (int i = tid; i < 1024; i += 256) s += out[4 + b * 1024 + i];
    red[tid] = s;
    __syncthreads();
    for (int off = 128; off > 0; off >>= 1) {
        if (tid < off) red[tid] += red[tid + off];
        __syncthreads();
    }
    if (tid == 0) out[b] = red[0];
}

// ---------------------------------------------------------------------------
extern "C" void kernel_launch(void* const* d_in, const int* in_sizes, int n_in,
                              void* d_out, int out_size)
{
    int off = (n_in >= 24) ? 0 : -1;   // nghost scalar may or may not materialize

    const int*    tmap = (const int*)   d_in[1];
    const float4* imdr = (const float4*)d_in[3];
    const float4* davg = (const float4*)d_in[5 + off];
    const float4* dstd = (const float4*)d_in[6 + off];
    const float*  tvec = (const float*) d_in[7 + off];
    const float*  tW0  = (const float*) d_in[8 + off];
    const float*  tb0  = (const float*) d_in[9 + off];
    const float*  eW0  = (const float*) d_in[10 + off];
    const float*  eb0  = (const float*) d_in[11 + off];
    const float*  eW1  = (const float*) d_in[12 + off];
    const float*  eb1  = (const float*) d_in[13 + off];
    const float*  eW2  = (const float*) d_in[14 + off];
    const float*  eb2  = (const float*) d_in[15 + off];
    const float*  fW0  = (const float*) d_in[16 + off];
    const float*  fb0  = (const float*) d_in[17 + off];
    const float*  fW1  = (const float*) d_in[18 + off];
    const float*  fb1  = (const float*) d_in[19 + off];
    const float*  fW2  = (const float*) d_in[20 + off];
    const float*  fb2  = (const float*) d_in[21 + off];
    const float*  fWf  = (const float*) d_in[22 + off];
    const float*  fbf  = (const float*) d_in[23 + off];
    float* out = (float*)d_out;

    cudaFuncSetAttribute(fit_kernel, cudaFuncAttributeMaxDynamicSharedMemorySize, 66560);

    sort_kernel<<<1, 1024>>>(tmap);
    build_tab_kernel<<<2 * K_TAB / 256, 256>>>(tvec, tW0, tb0, eW0, eb0,
                                               eW1, eb1, eW2, eb2);
    embed_kernel<<<4096, 256>>>(imdr, tmap, davg, dstd);
    fit_kernel<<<dim3(258, 2), 256, 66560>>>(tmap, fW0, fb0, fW1, fb1,
                                             fW2, fb2, fWf, fbf, out);
    etot_kernel<<<4, 256>>>(out);
}